// round 2
// baseline (speedup 1.0000x reference)
#include <cuda_runtime.h>
#include <cuda_bf16.h>
#include <cstdint>

// ---------------------------------------------------------------------------
// MultiHeadAttn: T=2048, B=4, N_HEAD=16, D_HEAD=64, D_MODEL=1024
//   q = h@wq^T ; k,v = h@wkv^T ; attn over klen with key-padding mask ;
//   out = LN(h + (attn@wo^T))
// Round 2: fix mask dtype (int32, not bytes). TF32 mma.sync everywhere.
// ---------------------------------------------------------------------------

#define T_LEN 2048
#define BATCH 4
#define NHEAD 16
#define DHEAD 64
#define DMODEL 1024
#define MROWS (T_LEN * BATCH)        // 8192
#define SCALE_ATT 0.125f             // 1/sqrt(64)

// Scratch (static device globals; no runtime allocation)
__device__ float g_Q[BATCH * NHEAD * T_LEN * DHEAD];   // [bh][t][d]
__device__ float g_K[BATCH * NHEAD * T_LEN * DHEAD];
__device__ float g_V[BATCH * NHEAD * T_LEN * DHEAD];
__device__ float g_att[MROWS * DMODEL];                // attn_vec, row m = t*4+b
__device__ float g_res[MROWS * DMODEL];                // h + attn_out

__device__ __forceinline__ float to_tf32(float x) {
    unsigned u;
    asm("cvt.rna.tf32.f32 %0, %1;" : "=r"(u) : "f"(x));
    return __uint_as_float(u);
}

__device__ __forceinline__ void mma_tf32(float& c0, float& c1, float& c2, float& c3,
                                         unsigned a0, unsigned a1, unsigned a2, unsigned a3,
                                         unsigned b0, unsigned b1) {
    asm volatile(
        "mma.sync.aligned.m16n8k8.row.col.f32.tf32.tf32.f32 "
        "{%0,%1,%2,%3},{%4,%5,%6,%7},{%8,%9},{%0,%1,%2,%3};"
        : "+f"(c0), "+f"(c1), "+f"(c2), "+f"(c3)
        : "r"(a0), "r"(a1), "r"(a2), "r"(a3), "r"(b0), "r"(b1));
}

__device__ __forceinline__ float clamp_m(float x) { return fmaxf(x, -1e30f); }

#define NEG_INF __int_as_float(0xff800000)

// ---------------------------------------------------------------------------
// GEMM core: C[m,n] = sum_k A[m,k] * W[n,k]   (A row-major, W row-major = NT)
// BM=BN=128, BK=32, 256 threads, 8 warps as 4x2, warp tile 32x64.
// ---------------------------------------------------------------------------
#define BK 32
#define APAD 4   // row stride 36 floats -> conflict-free frag loads (4g+tig)

// Kernel 1: QKV projection. grid (64, 24): bn<8 -> Q, 8..15 -> K, 16..23 -> V
__global__ __launch_bounds__(256) void qkv_gemm_kernel(
    const float* __restrict__ hmat,
    const float* __restrict__ wq,
    const float* __restrict__ wkv)
{
    __shared__ float As[128][BK + APAD];
    __shared__ float Bs[128][BK + APAD];
    const int bm = blockIdx.x, bn = blockIdx.y;
    const float* Wbase = (bn < 8) ? (wq + (size_t)bn * 128 * DMODEL)
                                  : (wkv + (size_t)(bn - 8) * 128 * DMODEL);
    const int tid = threadIdx.x;
    const int warp = tid >> 5, lane = tid & 31;
    const int wr = warp >> 1, wc = warp & 1;
    const int g = lane >> 2, tig = lane & 3;

    float acc[2][8][4];
#pragma unroll
    for (int i = 0; i < 2; i++)
#pragma unroll
        for (int j = 0; j < 8; j++)
#pragma unroll
            for (int e = 0; e < 4; e++) acc[i][j][e] = 0.f;

    for (int k0 = 0; k0 < DMODEL; k0 += BK) {
#pragma unroll
        for (int i = 0; i < 4; i++) {
            int s = tid + i * 256;       // 1024 float4 slots (128 rows x 8)
            int r = s >> 3, c4 = (s & 7) << 2;
            float4 va = *(const float4*)(hmat + (size_t)(bm * 128 + r) * DMODEL + k0 + c4);
            va.x = to_tf32(va.x); va.y = to_tf32(va.y); va.z = to_tf32(va.z); va.w = to_tf32(va.w);
            *(float4*)(&As[r][c4]) = va;
            float4 vb = *(const float4*)(Wbase + (size_t)r * DMODEL + k0 + c4);
            vb.x = to_tf32(vb.x); vb.y = to_tf32(vb.y); vb.z = to_tf32(vb.z); vb.w = to_tf32(vb.w);
            *(float4*)(&Bs[r][c4]) = vb;
        }
        __syncthreads();
#pragma unroll
        for (int kk = 0; kk < BK; kk += 8) {
            unsigned a[2][4];
#pragma unroll
            for (int mf = 0; mf < 2; mf++) {
                int r0 = wr * 32 + mf * 16;
                a[mf][0] = __float_as_uint(As[r0 + g][kk + tig]);
                a[mf][1] = __float_as_uint(As[r0 + g + 8][kk + tig]);
                a[mf][2] = __float_as_uint(As[r0 + g][kk + tig + 4]);
                a[mf][3] = __float_as_uint(As[r0 + g + 8][kk + tig + 4]);
            }
#pragma unroll
            for (int nf = 0; nf < 8; nf++) {
                int n0 = wc * 64 + nf * 8;
                unsigned b0 = __float_as_uint(Bs[n0 + g][kk + tig]);
                unsigned b1 = __float_as_uint(Bs[n0 + g][kk + tig + 4]);
#pragma unroll
                for (int mf = 0; mf < 2; mf++)
                    mma_tf32(acc[mf][nf][0], acc[mf][nf][1], acc[mf][nf][2], acc[mf][nf][3],
                             a[mf][0], a[mf][1], a[mf][2], a[mf][3], b0, b1);
            }
        }
        __syncthreads();
    }

    const int sec = bn >> 3;
    float* dst = (sec == 0) ? g_Q : ((sec == 1) ? g_K : g_V);
#pragma unroll
    for (int mf = 0; mf < 2; mf++)
#pragma unroll
        for (int nf = 0; nf < 8; nf++)
#pragma unroll
            for (int e = 0; e < 4; e++) {
                int rl = wr * 32 + mf * 16 + g + ((e >= 2) ? 8 : 0);
                int cl = wc * 64 + nf * 8 + tig * 2 + (e & 1);
                int m = bm * 128 + rl;
                int t = m >> 2, b = m & 3;
                int o = (bn & 7) * 128 + cl;
                int head = o >> 6, d = o & 63;
                dst[(((size_t)(b * NHEAD + head) * T_LEN + t) << 6) + d] = acc[mf][nf][e];
            }
}

// Kernel 3a: out projection + residual. grid (64, 8)
__global__ __launch_bounds__(256) void outproj_gemm_kernel(
    const float* __restrict__ hmat,
    const float* __restrict__ wo)
{
    __shared__ float As[128][BK + APAD];
    __shared__ float Bs[128][BK + APAD];
    const int bm = blockIdx.x, bn = blockIdx.y;
    const int tid = threadIdx.x;
    const int warp = tid >> 5, lane = tid & 31;
    const int wr = warp >> 1, wc = warp & 1;
    const int g = lane >> 2, tig = lane & 3;

    float acc[2][8][4];
#pragma unroll
    for (int i = 0; i < 2; i++)
#pragma unroll
        for (int j = 0; j < 8; j++)
#pragma unroll
            for (int e = 0; e < 4; e++) acc[i][j][e] = 0.f;

    for (int k0 = 0; k0 < DMODEL; k0 += BK) {
#pragma unroll
        for (int i = 0; i < 4; i++) {
            int s = tid + i * 256;
            int r = s >> 3, c4 = (s & 7) << 2;
            float4 va = *(const float4*)(g_att + (size_t)(bm * 128 + r) * DMODEL + k0 + c4);
            va.x = to_tf32(va.x); va.y = to_tf32(va.y); va.z = to_tf32(va.z); va.w = to_tf32(va.w);
            *(float4*)(&As[r][c4]) = va;
            float4 vb = *(const float4*)(wo + (size_t)(bn * 128 + r) * DMODEL + k0 + c4);
            vb.x = to_tf32(vb.x); vb.y = to_tf32(vb.y); vb.z = to_tf32(vb.z); vb.w = to_tf32(vb.w);
            *(float4*)(&Bs[r][c4]) = vb;
        }
        __syncthreads();
#pragma unroll
        for (int kk = 0; kk < BK; kk += 8) {
            unsigned a[2][4];
#pragma unroll
            for (int mf = 0; mf < 2; mf++) {
                int r0 = wr * 32 + mf * 16;
                a[mf][0] = __float_as_uint(As[r0 + g][kk + tig]);
                a[mf][1] = __float_as_uint(As[r0 + g + 8][kk + tig]);
                a[mf][2] = __float_as_uint(As[r0 + g][kk + tig + 4]);
                a[mf][3] = __float_as_uint(As[r0 + g + 8][kk + tig + 4]);
            }
#pragma unroll
            for (int nf = 0; nf < 8; nf++) {
                int n0 = wc * 64 + nf * 8;
                unsigned b0 = __float_as_uint(Bs[n0 + g][kk + tig]);
                unsigned b1 = __float_as_uint(Bs[n0 + g][kk + tig + 4]);
#pragma unroll
                for (int mf = 0; mf < 2; mf++)
                    mma_tf32(acc[mf][nf][0], acc[mf][nf][1], acc[mf][nf][2], acc[mf][nf][3],
                             a[mf][0], a[mf][1], a[mf][2], a[mf][3], b0, b1);
            }
        }
        __syncthreads();
    }

#pragma unroll
    for (int mf = 0; mf < 2; mf++)
#pragma unroll
        for (int nf = 0; nf < 8; nf++)
#pragma unroll
            for (int e = 0; e < 4; e++) {
                int rl = wr * 32 + mf * 16 + g + ((e >= 2) ? 8 : 0);
                int cl = wc * 64 + nf * 8 + tig * 2 + (e & 1);
                int m = bm * 128 + rl;
                int col = bn * 128 + cl;
                size_t idx = (size_t)m * DMODEL + col;
                g_res[idx] = acc[mf][nf][e] + hmat[idx];
            }
}

// ---------------------------------------------------------------------------
// Kernel 2: flash attention. grid (16 qblocks, 64 bh). 256 threads (8 warps),
// each warp owns 16 query rows. K-blocks of 128 streamed with online softmax.
// Mask is int32 (harness materializes jax bool as i32), nonzero = masked.
// ---------------------------------------------------------------------------
#define QSTRIDE 68
#define PSTRIDE 132
#define FLASH_SMEM_FLOATS (3 * 128 * QSTRIDE + 128 * PSTRIDE)
#define FLASH_SMEM_BYTES  (FLASH_SMEM_FLOATS * 4 + 512)

__global__ __launch_bounds__(256, 1) void flash_attn_kernel(
    const int* __restrict__ maskp)
{
    extern __shared__ float sm[];
    float (*Qs)[QSTRIDE] = (float (*)[QSTRIDE])sm;
    float (*Ks)[QSTRIDE] = (float (*)[QSTRIDE])(sm + 128 * QSTRIDE);
    float (*Vs)[QSTRIDE] = (float (*)[QSTRIDE])(sm + 2 * 128 * QSTRIDE);
    float (*Ps)[PSTRIDE] = (float (*)[PSTRIDE])(sm + 3 * 128 * QSTRIDE);
    int* msk = (int*)(sm + FLASH_SMEM_FLOATS);   // 128 ints

    const int qb = blockIdx.x, bh = blockIdx.y;
    const int b = bh >> 4, hh = bh & 15;
    const int tid = threadIdx.x;
    const int warp = tid >> 5, lane = tid & 31;
    const int g = lane >> 2, tig = lane & 3;
    const int row0 = warp * 16;

    const float* Qg = g_Q + (size_t)bh * T_LEN * DHEAD + (size_t)qb * 128 * DHEAD;
    const float* Kg = g_K + (size_t)bh * T_LEN * DHEAD;
    const float* Vg = g_V + (size_t)bh * T_LEN * DHEAD;

    // Load Q tile (128x64), tf32-rounded
#pragma unroll
    for (int i = 0; i < 8; i++) {
        int s = tid + i * 256;            // 2048 float4 slots
        int r = s >> 4, c4 = (s & 15) << 2;
        float4 v = *(const float4*)(Qg + (size_t)r * DHEAD + c4);
        v.x = to_tf32(v.x); v.y = to_tf32(v.y); v.z = to_tf32(v.z); v.w = to_tf32(v.w);
        *(float4*)(&Qs[r][c4]) = v;
    }

    float m_i[2] = {NEG_INF, NEG_INF};
    float l_i[2] = {0.f, 0.f};
    float o_acc[8][4];
#pragma unroll
    for (int nf = 0; nf < 8; nf++)
#pragma unroll
        for (int e = 0; e < 4; e++) o_acc[nf][e] = 0.f;

    for (int kb = 0; kb < 16; kb++) {
        __syncthreads();  // prior iter's K/V reads done; Q visible on iter 0
#pragma unroll
        for (int i = 0; i < 8; i++) {
            int s = tid + i * 256;
            int r = s >> 4, c4 = (s & 15) << 2;
            float4 vk = *(const float4*)(Kg + (size_t)(kb * 128 + r) * DHEAD + c4);
            vk.x = to_tf32(vk.x); vk.y = to_tf32(vk.y); vk.z = to_tf32(vk.z); vk.w = to_tf32(vk.w);
            *(float4*)(&Ks[r][c4]) = vk;
            float4 vv = *(const float4*)(Vg + (size_t)(kb * 128 + r) * DHEAD + c4);
            vv.x = to_tf32(vv.x); vv.y = to_tf32(vv.y); vv.z = to_tf32(vv.z); vv.w = to_tf32(vv.w);
            *(float4*)(&Vs[r][c4]) = vv;
        }
        // int32 key-padding mask: element index = key*BATCH + b
        if (tid < 128) msk[tid] = maskp[(size_t)(kb * 128 + tid) * BATCH + b];
        __syncthreads();

        // S = Q @ K^T  (warp: 16 rows x 128 cols)
        float s_acc[16][4];
#pragma unroll
        for (int nf = 0; nf < 16; nf++)
#pragma unroll
            for (int e = 0; e < 4; e++) s_acc[nf][e] = 0.f;
#pragma unroll
        for (int kk = 0; kk < 64; kk += 8) {
            unsigned a0 = __float_as_uint(Qs[row0 + g][kk + tig]);
            unsigned a1 = __float_as_uint(Qs[row0 + g + 8][kk + tig]);
            unsigned a2 = __float_as_uint(Qs[row0 + g][kk + tig + 4]);
            unsigned a3 = __float_as_uint(Qs[row0 + g + 8][kk + tig + 4]);
#pragma unroll
            for (int nf = 0; nf < 16; nf++) {
                unsigned b0 = __float_as_uint(Ks[nf * 8 + g][kk + tig]);
                unsigned b1 = __float_as_uint(Ks[nf * 8 + g][kk + tig + 4]);
                mma_tf32(s_acc[nf][0], s_acc[nf][1], s_acc[nf][2], s_acc[nf][3],
                         a0, a1, a2, a3, b0, b1);
            }
        }

        // scale + mask + row max
        float mx[2] = {NEG_INF, NEG_INF};
#pragma unroll
        for (int nf = 0; nf < 16; nf++) {
            int c0 = nf * 8 + tig * 2;
            bool k0m = msk[c0] != 0, k1m = msk[c0 + 1] != 0;
            s_acc[nf][0] = k0m ? NEG_INF : s_acc[nf][0] * SCALE_ATT;
            s_acc[nf][1] = k1m ? NEG_INF : s_acc[nf][1] * SCALE_ATT;
            s_acc[nf][2] = k0m ? NEG_INF : s_acc[nf][2] * SCALE_ATT;
            s_acc[nf][3] = k1m ? NEG_INF : s_acc[nf][3] * SCALE_ATT;
            mx[0] = fmaxf(mx[0], fmaxf(s_acc[nf][0], s_acc[nf][1]));
            mx[1] = fmaxf(mx[1], fmaxf(s_acc[nf][2], s_acc[nf][3]));
        }
#pragma unroll
        for (int off = 1; off < 4; off <<= 1) {
            mx[0] = fmaxf(mx[0], __shfl_xor_sync(0xffffffffu, mx[0], off));
            mx[1] = fmaxf(mx[1], __shfl_xor_sync(0xffffffffu, mx[1], off));
        }

        float alpha[2], mc[2];
#pragma unroll
        for (int r = 0; r < 2; r++) {
            float mnew = fmaxf(m_i[r], mx[r]);
            alpha[r] = __expf(clamp_m(m_i[r]) - clamp_m(mnew));
            m_i[r] = mnew;
            mc[r] = clamp_m(mnew);
        }

        // p = exp(s - m), row sums, stash tf32 P into smem
        float ps[2] = {0.f, 0.f};
#pragma unroll
        for (int nf = 0; nf < 16; nf++) {
            int c0 = nf * 8 + tig * 2;
            float p0 = __expf(s_acc[nf][0] - mc[0]);
            float p1 = __expf(s_acc[nf][1] - mc[0]);
            float p2 = __expf(s_acc[nf][2] - mc[1]);
            float p3 = __expf(s_acc[nf][3] - mc[1]);
            ps[0] += p0 + p1;
            ps[1] += p2 + p3;
            Ps[row0 + g][c0] = to_tf32(p0);
            Ps[row0 + g][c0 + 1] = to_tf32(p1);
            Ps[row0 + g + 8][c0] = to_tf32(p2);
            Ps[row0 + g + 8][c0 + 1] = to_tf32(p3);
        }
#pragma unroll
        for (int off = 1; off < 4; off <<= 1) {
            ps[0] += __shfl_xor_sync(0xffffffffu, ps[0], off);
            ps[1] += __shfl_xor_sync(0xffffffffu, ps[1], off);
        }
        l_i[0] = l_i[0] * alpha[0] + ps[0];
        l_i[1] = l_i[1] * alpha[1] + ps[1];

#pragma unroll
        for (int nf = 0; nf < 8; nf++) {
            o_acc[nf][0] *= alpha[0];
            o_acc[nf][1] *= alpha[0];
            o_acc[nf][2] *= alpha[1];
            o_acc[nf][3] *= alpha[1];
        }

        __syncwarp();  // band-local P writes visible to all lanes of this warp

        // O += P @ V  (warp: own 16 rows, k over 128 keys)
#pragma unroll
        for (int kk = 0; kk < 128; kk += 8) {
            unsigned a0 = __float_as_uint(Ps[row0 + g][kk + tig]);
            unsigned a1 = __float_as_uint(Ps[row0 + g + 8][kk + tig]);
            unsigned a2 = __float_as_uint(Ps[row0 + g][kk + tig + 4]);
            unsigned a3 = __float_as_uint(Ps[row0 + g + 8][kk + tig + 4]);
#pragma unroll
            for (int nf = 0; nf < 8; nf++) {
                unsigned b0 = __float_as_uint(Vs[kk + tig][nf * 8 + g]);
                unsigned b1 = __float_as_uint(Vs[kk + tig + 4][nf * 8 + g]);
                mma_tf32(o_acc[nf][0], o_acc[nf][1], o_acc[nf][2], o_acc[nf][3],
                         a0, a1, a2, a3, b0, b1);
            }
        }
    }

    float inv_l[2] = {1.f / l_i[0], 1.f / l_i[1]};
#pragma unroll
    for (int nf = 0; nf < 8; nf++)
#pragma unroll
        for (int e = 0; e < 4; e++) {
            int t = qb * 128 + row0 + g + ((e >= 2) ? 8 : 0);
            int d = nf * 8 + tig * 2 + (e & 1);
            int m = t * BATCH + b;
            g_att[(size_t)m * DMODEL + hh * DHEAD + d] = o_acc[nf][e] * inv_l[e >= 2 ? 1 : 0];
        }
}

// ---------------------------------------------------------------------------
// Kernel 3b: LayerNorm per row (1024 elems), two-pass, register-resident.
// ---------------------------------------------------------------------------
__device__ __forceinline__ float block_sum256(float v) {
    __shared__ float red[8];
#pragma unroll
    for (int off = 16; off > 0; off >>= 1) v += __shfl_xor_sync(0xffffffffu, v, off);
    if ((threadIdx.x & 31) == 0) red[threadIdx.x >> 5] = v;
    __syncthreads();
    v = red[0] + red[1] + red[2] + red[3] + red[4] + red[5] + red[6] + red[7];
    __syncthreads();
    return v;
}

__global__ __launch_bounds__(256) void layernorm_kernel(
    const float* __restrict__ lng, const float* __restrict__ lnb,
    float* __restrict__ out)
{
    const int row = blockIdx.x;
    const int tid = threadIdx.x;
    const float* x = g_res + (size_t)row * DMODEL;
    float4 v = *(const float4*)(x + tid * 4);
    float s = block_sum256(v.x + v.y + v.z + v.w);
    float mu = s * (1.f / DMODEL);
    float dx = v.x - mu, dy = v.y - mu, dz = v.z - mu, dw = v.w - mu;
    float sq = block_sum256(dx * dx + dy * dy + dz * dz + dw * dw);
    float var = sq * (1.f / DMODEL);
    float rstd = rsqrtf(var + 1e-5f);
    float4 gg = *(const float4*)(lng + tid * 4);
    float4 bb = *(const float4*)(lnb + tid * 4);
    float4 r;
    r.x = dx * rstd * gg.x + bb.x;
    r.y = dy * rstd * gg.y + bb.y;
    r.z = dz * rstd * gg.z + bb.z;
    r.w = dw * rstd * gg.w + bb.w;
    *(float4*)(out + (size_t)row * DMODEL + tid * 4) = r;
}

// ---------------------------------------------------------------------------
extern "C" void kernel_launch(void* const* d_in, const int* in_sizes, int n_in,
                              void* d_out, int out_size) {
    const float* h = (const float*)d_in[0];
    const int* mask = (const int*)d_in[1];
    const float* wq = (const float*)d_in[2];
    const float* wkv = (const float*)d_in[3];
    const float* wo = (const float*)d_in[4];
    const float* lng = (const float*)d_in[5];
    const float* lnb = (const float*)d_in[6];
    float* out = (float*)d_out;

    cudaFuncSetAttribute(flash_attn_kernel,
                         cudaFuncAttributeMaxDynamicSharedMemorySize, FLASH_SMEM_BYTES);

    qkv_gemm_kernel<<<dim3(64, 24), 256>>>(h, wq, wkv);
    flash_attn_kernel<<<dim3(16, 64), 256, FLASH_SMEM_BYTES>>>(mask);
    outproj_gemm_kernel<<<dim3(64, 8), 256>>>(h, wo);
    layernorm_kernel<<<MROWS, 256>>>(lng, lnb, out);
}

// round 3
// speedup vs baseline: 2.0257x; 2.0257x over previous
#include <cuda_runtime.h>
#include <cuda_fp16.h>
#include <cstdint>

// ---------------------------------------------------------------------------
// MultiHeadAttn: T=2048, B=4, N_HEAD=16, D_HEAD=64, D_MODEL=1024
// Round 3: all MMAs switched to fp16 m16n8k16 (same mantissa as tf32, fp32
// accum), half-precision scratch, ldmatrix.trans for V, 2 CTA/SM flash.
// ---------------------------------------------------------------------------

#define T_LEN 2048
#define BATCH 4
#define NHEAD 16
#define DHEAD 64
#define DMODEL 1024
#define MROWS (T_LEN * BATCH)        // 8192
#define SCALE_ATT 0.125f             // 1/sqrt(64)

// Scratch (static device globals; no runtime allocation)
__device__ __half g_Q[BATCH * NHEAD * T_LEN * DHEAD];   // [bh][t][d]
__device__ __half g_K[BATCH * NHEAD * T_LEN * DHEAD];
__device__ __half g_V[BATCH * NHEAD * T_LEN * DHEAD];
__device__ __half g_att[MROWS * DMODEL];                // attn_vec, row m = t*4+b
__device__ float  g_res[MROWS * DMODEL];                // h + attn_out

#define NEG_INF __int_as_float(0xff800000)

__device__ __forceinline__ float clamp_m(float x) { return fmaxf(x, -1e30f); }

__device__ __forceinline__ void mma_f16(float& c0, float& c1, float& c2, float& c3,
                                        unsigned a0, unsigned a1, unsigned a2, unsigned a3,
                                        unsigned b0, unsigned b1) {
    asm volatile(
        "mma.sync.aligned.m16n8k16.row.col.f32.f16.f16.f32 "
        "{%0,%1,%2,%3},{%4,%5,%6,%7},{%8,%9},{%0,%1,%2,%3};"
        : "+f"(c0), "+f"(c1), "+f"(c2), "+f"(c3)
        : "r"(a0), "r"(a1), "r"(a2), "r"(a3), "r"(b0), "r"(b1));
}

__device__ __forceinline__ void ldsm_x4_trans(unsigned& r0, unsigned& r1,
                                              unsigned& r2, unsigned& r3,
                                              const __half* p) {
    unsigned sa = (unsigned)__cvta_generic_to_shared(p);
    asm volatile("ldmatrix.sync.aligned.m8n8.x4.trans.shared.b16 {%0,%1,%2,%3}, [%4];"
                 : "=r"(r0), "=r"(r1), "=r"(r2), "=r"(r3) : "r"(sa));
}

__device__ __forceinline__ unsigned pack_h2(float a, float b) {
    __half2 h = __floats2half2_rn(a, b);
    return *(unsigned*)&h;
}

// ---------------------------------------------------------------------------
// fp16 GEMM core: C[m,n] = sum_k A[m,k] * W[n,k]  (NT). BM=BN=128, BK=64,
// 256 threads, 8 warps 4x2, warp tile 32x64. Smem half, stride 72 (144B).
// ---------------------------------------------------------------------------
#define BK 64
#define HSTR 72   // half stride per row (64 + 8 pad)

// Kernel 1: QKV projection. grid (64, 24): bn<8 -> Q, 8..15 -> K, 16..23 -> V
__global__ __launch_bounds__(256) void qkv_gemm_kernel(
    const float* __restrict__ hmat,
    const float* __restrict__ wq,
    const float* __restrict__ wkv)
{
    __shared__ __half As[128][HSTR];
    __shared__ __half Bs[128][HSTR];
    const int bm = blockIdx.x, bn = blockIdx.y;
    const float* Wbase = (bn < 8) ? (wq + (size_t)bn * 128 * DMODEL)
                                  : (wkv + (size_t)(bn - 8) * 128 * DMODEL);
    const int tid = threadIdx.x;
    const int warp = tid >> 5, lane = tid & 31;
    const int wr = warp >> 1, wc = warp & 1;
    const int g = lane >> 2, tig = lane & 3;

    float acc[2][8][4];
#pragma unroll
    for (int i = 0; i < 2; i++)
#pragma unroll
        for (int j = 0; j < 8; j++)
#pragma unroll
            for (int e = 0; e < 4; e++) acc[i][j][e] = 0.f;

    for (int k0 = 0; k0 < DMODEL; k0 += BK) {
#pragma unroll
        for (int i = 0; i < 8; i++) {
            int s = tid + i * 256;       // 2048 float4 slots: 128 rows x 16
            int r = s >> 4, c4 = (s & 15) << 2;
            float4 va = *(const float4*)(hmat + (size_t)(bm * 128 + r) * DMODEL + k0 + c4);
            uint2 ua = {pack_h2(va.x, va.y), pack_h2(va.z, va.w)};
            *(uint2*)(&As[r][c4]) = ua;
            float4 vb = *(const float4*)(Wbase + (size_t)r * DMODEL + k0 + c4);
            uint2 ub = {pack_h2(vb.x, vb.y), pack_h2(vb.z, vb.w)};
            *(uint2*)(&Bs[r][c4]) = ub;
        }
        __syncthreads();
#pragma unroll
        for (int kk = 0; kk < BK; kk += 16) {
            unsigned a[2][4];
#pragma unroll
            for (int mf = 0; mf < 2; mf++) {
                int r0 = wr * 32 + mf * 16;
                a[mf][0] = *(const unsigned*)(&As[r0 + g][kk + 2 * tig]);
                a[mf][1] = *(const unsigned*)(&As[r0 + g + 8][kk + 2 * tig]);
                a[mf][2] = *(const unsigned*)(&As[r0 + g][kk + 2 * tig + 8]);
                a[mf][3] = *(const unsigned*)(&As[r0 + g + 8][kk + 2 * tig + 8]);
            }
#pragma unroll
            for (int nf = 0; nf < 8; nf++) {
                int n0 = wc * 64 + nf * 8;
                unsigned b0 = *(const unsigned*)(&Bs[n0 + g][kk + 2 * tig]);
                unsigned b1 = *(const unsigned*)(&Bs[n0 + g][kk + 2 * tig + 8]);
#pragma unroll
                for (int mf = 0; mf < 2; mf++)
                    mma_f16(acc[mf][nf][0], acc[mf][nf][1], acc[mf][nf][2], acc[mf][nf][3],
                            a[mf][0], a[mf][1], a[mf][2], a[mf][3], b0, b1);
            }
        }
        __syncthreads();
    }

    const int sec = bn >> 3;
    __half* dst = (sec == 0) ? g_Q : ((sec == 1) ? g_K : g_V);
#pragma unroll
    for (int mf = 0; mf < 2; mf++)
#pragma unroll
        for (int nf = 0; nf < 8; nf++)
#pragma unroll
            for (int eh = 0; eh < 2; eh++) {   // eh=0 -> row g (e0,e1); eh=1 -> row g+8 (e2,e3)
                int rl = wr * 32 + mf * 16 + g + eh * 8;
                int cl = wc * 64 + nf * 8 + tig * 2;
                int m = bm * 128 + rl;
                int t = m >> 2, b = m & 3;
                int o = (bn & 7) * 128 + cl;
                int head = o >> 6, d = o & 63;
                unsigned pv = pack_h2(acc[mf][nf][eh * 2], acc[mf][nf][eh * 2 + 1]);
                *(unsigned*)(&dst[(((size_t)(b * NHEAD + head) * T_LEN + t) << 6) + d]) = pv;
            }
}

// Kernel 3a: out projection + residual. grid (64, 8). A = g_att (half).
__global__ __launch_bounds__(256) void outproj_gemm_kernel(
    const float* __restrict__ hmat,
    const float* __restrict__ wo)
{
    __shared__ __half As[128][HSTR];
    __shared__ __half Bs[128][HSTR];
    const int bm = blockIdx.x, bn = blockIdx.y;
    const int tid = threadIdx.x;
    const int warp = tid >> 5, lane = tid & 31;
    const int wr = warp >> 1, wc = warp & 1;
    const int g = lane >> 2, tig = lane & 3;

    float acc[2][8][4];
#pragma unroll
    for (int i = 0; i < 2; i++)
#pragma unroll
        for (int j = 0; j < 8; j++)
#pragma unroll
            for (int e = 0; e < 4; e++) acc[i][j][e] = 0.f;

    for (int k0 = 0; k0 < DMODEL; k0 += BK) {
        // A tile: half, direct 16B copies (1024 slots of 8 halves)
#pragma unroll
        for (int i = 0; i < 4; i++) {
            int s = tid + i * 256;
            int r = s >> 3, c8 = (s & 7) << 3;
            uint4 u = *(const uint4*)(g_att + (size_t)(bm * 128 + r) * DMODEL + k0 + c8);
            *(uint4*)(&As[r][c8]) = u;
        }
        // B tile: fp32 -> half
#pragma unroll
        for (int i = 0; i < 8; i++) {
            int s = tid + i * 256;
            int r = s >> 4, c4 = (s & 15) << 2;
            float4 vb = *(const float4*)(wo + (size_t)(bn * 128 + r) * DMODEL + k0 + c4);
            uint2 ub = {pack_h2(vb.x, vb.y), pack_h2(vb.z, vb.w)};
            *(uint2*)(&Bs[r][c4]) = ub;
        }
        __syncthreads();
#pragma unroll
        for (int kk = 0; kk < BK; kk += 16) {
            unsigned a[2][4];
#pragma unroll
            for (int mf = 0; mf < 2; mf++) {
                int r0 = wr * 32 + mf * 16;
                a[mf][0] = *(const unsigned*)(&As[r0 + g][kk + 2 * tig]);
                a[mf][1] = *(const unsigned*)(&As[r0 + g + 8][kk + 2 * tig]);
                a[mf][2] = *(const unsigned*)(&As[r0 + g][kk + 2 * tig + 8]);
                a[mf][3] = *(const unsigned*)(&As[r0 + g + 8][kk + 2 * tig + 8]);
            }
#pragma unroll
            for (int nf = 0; nf < 8; nf++) {
                int n0 = wc * 64 + nf * 8;
                unsigned b0 = *(const unsigned*)(&Bs[n0 + g][kk + 2 * tig]);
                unsigned b1 = *(const unsigned*)(&Bs[n0 + g][kk + 2 * tig + 8]);
#pragma unroll
                for (int mf = 0; mf < 2; mf++)
                    mma_f16(acc[mf][nf][0], acc[mf][nf][1], acc[mf][nf][2], acc[mf][nf][3],
                            a[mf][0], a[mf][1], a[mf][2], a[mf][3], b0, b1);
            }
        }
        __syncthreads();
    }

#pragma unroll
    for (int mf = 0; mf < 2; mf++)
#pragma unroll
        for (int nf = 0; nf < 8; nf++)
#pragma unroll
            for (int e = 0; e < 4; e++) {
                int rl = wr * 32 + mf * 16 + g + ((e >= 2) ? 8 : 0);
                int cl = wc * 64 + nf * 8 + tig * 2 + (e & 1);
                int m = bm * 128 + rl;
                int col = bn * 128 + cl;
                size_t idx = (size_t)m * DMODEL + col;
                g_res[idx] = acc[mf][nf][e] + hmat[idx];
            }
}

// ---------------------------------------------------------------------------
// Kernel 2: flash attention, fp16. grid (16 qblocks, 64 bh). 256 threads.
// Smem ~90.6KB -> 2 CTAs/SM. Mask int32, nonzero = masked.
// ---------------------------------------------------------------------------
#define PSTR 136   // halves per Ps row (128 + 8 pad)
#define FLASH_SMEM_BYTES (3 * 128 * HSTR * 2 + 128 * PSTR * 2 + 512)

__global__ __launch_bounds__(256, 2) void flash_attn_kernel(
    const int* __restrict__ maskp)
{
    extern __shared__ __half sm[];
    __half (*Qs)[HSTR] = (__half (*)[HSTR])sm;
    __half (*Ks)[HSTR] = (__half (*)[HSTR])(sm + 128 * HSTR);
    __half (*Vs)[HSTR] = (__half (*)[HSTR])(sm + 2 * 128 * HSTR);
    __half (*Ps)[PSTR] = (__half (*)[PSTR])(sm + 3 * 128 * HSTR);
    int* msk = (int*)(sm + 3 * 128 * HSTR + 128 * PSTR);   // 128 ints

    const int qb = blockIdx.x, bh = blockIdx.y;
    const int b = bh >> 4, hh = bh & 15;
    const int tid = threadIdx.x;
    const int warp = tid >> 5, lane = tid & 31;
    const int g = lane >> 2, tig = lane & 3;
    const int row0 = warp * 16;

    const __half* Qg = g_Q + (size_t)bh * T_LEN * DHEAD + (size_t)qb * 128 * DHEAD;
    const __half* Kg = g_K + (size_t)bh * T_LEN * DHEAD;
    const __half* Vg = g_V + (size_t)bh * T_LEN * DHEAD;

    // Load Q tile (128x64 half): 1024 slots of 8 halves (16B)
#pragma unroll
    for (int i = 0; i < 4; i++) {
        int s = tid + i * 256;
        int r = s >> 3, c8 = (s & 7) << 3;
        uint4 u = *(const uint4*)(Qg + (size_t)r * DHEAD + c8);
        *(uint4*)(&Qs[r][c8]) = u;
    }

    float m_i[2] = {NEG_INF, NEG_INF};
    float l_i[2] = {0.f, 0.f};
    float o_acc[8][4];
#pragma unroll
    for (int nf = 0; nf < 8; nf++)
#pragma unroll
        for (int e = 0; e < 4; e++) o_acc[nf][e] = 0.f;

    for (int kb = 0; kb < 16; kb++) {
        __syncthreads();  // prior iter's K/V reads done; Q visible on iter 0
#pragma unroll
        for (int i = 0; i < 4; i++) {
            int s = tid + i * 256;
            int r = s >> 3, c8 = (s & 7) << 3;
            uint4 uk = *(const uint4*)(Kg + (size_t)(kb * 128 + r) * DHEAD + c8);
            *(uint4*)(&Ks[r][c8]) = uk;
            uint4 uv = *(const uint4*)(Vg + (size_t)(kb * 128 + r) * DHEAD + c8);
            *(uint4*)(&Vs[r][c8]) = uv;
        }
        if (tid < 128) msk[tid] = maskp[(size_t)(kb * 128 + tid) * BATCH + b];
        __syncthreads();

        // S = Q @ K^T  (warp: 16 rows x 128 cols), 4 k16 steps over d=64
        float s_acc[16][4];
#pragma unroll
        for (int nf = 0; nf < 16; nf++)
#pragma unroll
            for (int e = 0; e < 4; e++) s_acc[nf][e] = 0.f;
#pragma unroll
        for (int kk = 0; kk < 64; kk += 16) {
            unsigned a0 = *(const unsigned*)(&Qs[row0 + g][kk + 2 * tig]);
            unsigned a1 = *(const unsigned*)(&Qs[row0 + g + 8][kk + 2 * tig]);
            unsigned a2 = *(const unsigned*)(&Qs[row0 + g][kk + 2 * tig + 8]);
            unsigned a3 = *(const unsigned*)(&Qs[row0 + g + 8][kk + 2 * tig + 8]);
#pragma unroll
            for (int nf = 0; nf < 16; nf++) {
                unsigned b0 = *(const unsigned*)(&Ks[nf * 8 + g][kk + 2 * tig]);
                unsigned b1 = *(const unsigned*)(&Ks[nf * 8 + g][kk + 2 * tig + 8]);
                mma_f16(s_acc[nf][0], s_acc[nf][1], s_acc[nf][2], s_acc[nf][3],
                        a0, a1, a2, a3, b0, b1);
            }
        }

        // scale + mask + row max
        float mx[2] = {NEG_INF, NEG_INF};
#pragma unroll
        for (int nf = 0; nf < 16; nf++) {
            int c0 = nf * 8 + tig * 2;
            bool k0m = msk[c0] != 0, k1m = msk[c0 + 1] != 0;
            s_acc[nf][0] = k0m ? NEG_INF : s_acc[nf][0] * SCALE_ATT;
            s_acc[nf][1] = k1m ? NEG_INF : s_acc[nf][1] * SCALE_ATT;
            s_acc[nf][2] = k0m ? NEG_INF : s_acc[nf][2] * SCALE_ATT;
            s_acc[nf][3] = k1m ? NEG_INF : s_acc[nf][3] * SCALE_ATT;
            mx[0] = fmaxf(mx[0], fmaxf(s_acc[nf][0], s_acc[nf][1]));
            mx[1] = fmaxf(mx[1], fmaxf(s_acc[nf][2], s_acc[nf][3]));
        }
#pragma unroll
        for (int off = 1; off < 4; off <<= 1) {
            mx[0] = fmaxf(mx[0], __shfl_xor_sync(0xffffffffu, mx[0], off));
            mx[1] = fmaxf(mx[1], __shfl_xor_sync(0xffffffffu, mx[1], off));
        }

        float alpha[2], mc[2];
#pragma unroll
        for (int r = 0; r < 2; r++) {
            float mnew = fmaxf(m_i[r], mx[r]);
            alpha[r] = __expf(clamp_m(m_i[r]) - clamp_m(mnew));
            m_i[r] = mnew;
            mc[r] = clamp_m(mnew);
        }

        // p = exp(s - m), row sums, stash half P into smem
        float ps[2] = {0.f, 0.f};
#pragma unroll
        for (int nf = 0; nf < 16; nf++) {
            int c0 = nf * 8 + tig * 2;
            float p0 = __expf(s_acc[nf][0] - mc[0]);
            float p1 = __expf(s_acc[nf][1] - mc[0]);
            float p2 = __expf(s_acc[nf][2] - mc[1]);
            float p3 = __expf(s_acc[nf][3] - mc[1]);
            ps[0] += p0 + p1;
            ps[1] += p2 + p3;
            *(unsigned*)(&Ps[row0 + g][c0]) = pack_h2(p0, p1);
            *(unsigned*)(&Ps[row0 + g + 8][c0]) = pack_h2(p2, p3);
        }
#pragma unroll
        for (int off = 1; off < 4; off <<= 1) {
            ps[0] += __shfl_xor_sync(0xffffffffu, ps[0], off);
            ps[1] += __shfl_xor_sync(0xffffffffu, ps[1], off);
        }
        l_i[0] = l_i[0] * alpha[0] + ps[0];
        l_i[1] = l_i[1] * alpha[1] + ps[1];

#pragma unroll
        for (int nf = 0; nf < 8; nf++) {
            o_acc[nf][0] *= alpha[0];
            o_acc[nf][1] *= alpha[0];
            o_acc[nf][2] *= alpha[1];
            o_acc[nf][3] *= alpha[1];
        }

        __syncwarp();  // own-band Ps writes visible within warp

        // O += P @ V : 8 k16 steps over 128 keys; V frags via ldmatrix.trans
#pragma unroll
        for (int kk = 0; kk < 128; kk += 16) {
            unsigned a0 = *(const unsigned*)(&Ps[row0 + g][kk + 2 * tig]);
            unsigned a1 = *(const unsigned*)(&Ps[row0 + g + 8][kk + 2 * tig]);
            unsigned a2 = *(const unsigned*)(&Ps[row0 + g][kk + 2 * tig + 8]);
            unsigned a3 = *(const unsigned*)(&Ps[row0 + g + 8][kk + 2 * tig + 8]);
#pragma unroll
            for (int nfp = 0; nfp < 4; nfp++) {
                // 4 x (8x8) tiles: (k0-7,n0-7),(k8-15,n0-7),(k0-7,n8-15),(k8-15,n8-15)
                int mt = lane >> 3, ri = lane & 7;
                const __half* vp = &Vs[kk + ri + ((mt & 1) << 3)][nfp * 16 + ((mt >> 1) << 3)];
                unsigned r0, r1, r2, r3;
                ldsm_x4_trans(r0, r1, r2, r3, vp);
                int nf = nfp * 2;
                mma_f16(o_acc[nf][0], o_acc[nf][1], o_acc[nf][2], o_acc[nf][3],
                        a0, a1, a2, a3, r0, r1);
                mma_f16(o_acc[nf + 1][0], o_acc[nf + 1][1], o_acc[nf + 1][2], o_acc[nf + 1][3],
                        a0, a1, a2, a3, r2, r3);
            }
        }
    }

    float inv_l[2] = {1.f / l_i[0], 1.f / l_i[1]};
#pragma unroll
    for (int nf = 0; nf < 8; nf++)
#pragma unroll
        for (int eh = 0; eh < 2; eh++) {
            int t = qb * 128 + row0 + g + eh * 8;
            int d = nf * 8 + tig * 2;
            int m = t * BATCH + b;
            unsigned pv = pack_h2(o_acc[nf][eh * 2] * inv_l[eh],
                                  o_acc[nf][eh * 2 + 1] * inv_l[eh]);
            *(unsigned*)(&g_att[(size_t)m * DMODEL + hh * DHEAD + d]) = pv;
        }
}

// ---------------------------------------------------------------------------
// Kernel 3b: LayerNorm per row (1024 elems), two-pass, register-resident.
// ---------------------------------------------------------------------------
__device__ __forceinline__ float block_sum256(float v) {
    __shared__ float red[8];
#pragma unroll
    for (int off = 16; off > 0; off >>= 1) v += __shfl_xor_sync(0xffffffffu, v, off);
    if ((threadIdx.x & 31) == 0) red[threadIdx.x >> 5] = v;
    __syncthreads();
    v = red[0] + red[1] + red[2] + red[3] + red[4] + red[5] + red[6] + red[7];
    __syncthreads();
    return v;
}

__global__ __launch_bounds__(256) void layernorm_kernel(
    const float* __restrict__ lng, const float* __restrict__ lnb,
    float* __restrict__ out)
{
    const int row = blockIdx.x;
    const int tid = threadIdx.x;
    const float* x = g_res + (size_t)row * DMODEL;
    float4 v = *(const float4*)(x + tid * 4);
    float s = block_sum256(v.x + v.y + v.z + v.w);
    float mu = s * (1.f / DMODEL);
    float dx = v.x - mu, dy = v.y - mu, dz = v.z - mu, dw = v.w - mu;
    float sq = block_sum256(dx * dx + dy * dy + dz * dz + dw * dw);
    float var = sq * (1.f / DMODEL);
    float rstd = rsqrtf(var + 1e-5f);
    float4 gg = *(const float4*)(lng + tid * 4);
    float4 bb = *(const float4*)(lnb + tid * 4);
    float4 r;
    r.x = dx * rstd * gg.x + bb.x;
    r.y = dy * rstd * gg.y + bb.y;
    r.z = dz * rstd * gg.z + bb.z;
    r.w = dw * rstd * gg.w + bb.w;
    *(float4*)(out + (size_t)row * DMODEL + tid * 4) = r;
}

// ---------------------------------------------------------------------------
extern "C" void kernel_launch(void* const* d_in, const int* in_sizes, int n_in,
                              void* d_out, int out_size) {
    const float* h = (const float*)d_in[0];
    const int* mask = (const int*)d_in[1];
    const float* wq = (const float*)d_in[2];
    const float* wkv = (const float*)d_in[3];
    const float* wo = (const float*)d_in[4];
    const float* lng = (const float*)d_in[5];
    const float* lnb = (const float*)d_in[6];
    float* out = (float*)d_out;

    cudaFuncSetAttribute(flash_attn_kernel,
                         cudaFuncAttributeMaxDynamicSharedMemorySize, FLASH_SMEM_BYTES);

    qkv_gemm_kernel<<<dim3(64, 24), 256>>>(h, wq, wkv);
    flash_attn_kernel<<<dim3(16, 64), 256, FLASH_SMEM_BYTES>>>(mask);
    outproj_gemm_kernel<<<dim3(64, 8), 256>>>(h, wo);
    layernorm_kernel<<<MROWS, 256>>>(lng, lnb, out);
}

// round 5
// speedup vs baseline: 2.4537x; 1.2113x over previous
#include <cuda_runtime.h>
#include <cuda_fp16.h>
#include <cstdint>

// ---------------------------------------------------------------------------
// MultiHeadAttn: T=2048, B=4, N_HEAD=16, D_HEAD=64, D_MODEL=1024
// Round 5: Round 4 design with the flash K/V cp.async loader fixed (full
// 128x64 tile staged: 1024 chunks, not 512).
// ---------------------------------------------------------------------------

#define T_LEN 2048
#define BATCH 4
#define NHEAD 16
#define DHEAD 64
#define DMODEL 1024
#define MROWS (T_LEN * BATCH)        // 8192
#define SCALE_ATT 0.125f             // 1/sqrt(64)

// Scratch (static device globals; no runtime allocation)
__device__ __half g_hh[MROWS * DMODEL];                 // h in half
__device__ __half g_wqkvh[3072 * DMODEL];               // [wq rows 0..1023 | wkv rows]
__device__ __half g_woh[DMODEL * DMODEL];
__device__ __align__(16) unsigned char g_mskb[BATCH * T_LEN];  // [b][t] 1 = masked
__device__ __half g_Q[BATCH * NHEAD * T_LEN * DHEAD];   // [bh][t][d]
__device__ __half g_K[BATCH * NHEAD * T_LEN * DHEAD];
__device__ __half g_V[BATCH * NHEAD * T_LEN * DHEAD];
__device__ __half g_att[MROWS * DMODEL];                // attn_vec, row m = t*4+b
__device__ float  g_res[MROWS * DMODEL];                // h + attn_out

#define NEG_INF __int_as_float(0xff800000)

__device__ __forceinline__ float clamp_m(float x) { return fmaxf(x, -1e30f); }

__device__ __forceinline__ void mma_f16(float& c0, float& c1, float& c2, float& c3,
                                        unsigned a0, unsigned a1, unsigned a2, unsigned a3,
                                        unsigned b0, unsigned b1) {
    asm volatile(
        "mma.sync.aligned.m16n8k16.row.col.f32.f16.f16.f32 "
        "{%0,%1,%2,%3},{%4,%5,%6,%7},{%8,%9},{%0,%1,%2,%3};"
        : "+f"(c0), "+f"(c1), "+f"(c2), "+f"(c3)
        : "r"(a0), "r"(a1), "r"(a2), "r"(a3), "r"(b0), "r"(b1));
}

__device__ __forceinline__ void ldsm_x4_trans(unsigned& r0, unsigned& r1,
                                              unsigned& r2, unsigned& r3,
                                              const __half* p) {
    unsigned sa = (unsigned)__cvta_generic_to_shared(p);
    asm volatile("ldmatrix.sync.aligned.m8n8.x4.trans.shared.b16 {%0,%1,%2,%3}, [%4];"
                 : "=r"(r0), "=r"(r1), "=r"(r2), "=r"(r3) : "r"(sa));
}

__device__ __forceinline__ unsigned pack_h2(float a, float b) {
    __half2 h = __floats2half2_rn(a, b);
    return *(unsigned*)&h;
}

__device__ __forceinline__ void cp16(const void* smem_dst, const void* gsrc) {
    unsigned sa = (unsigned)__cvta_generic_to_shared(smem_dst);
    unsigned long long ga = (unsigned long long)__cvta_generic_to_global(gsrc);
    asm volatile("cp.async.cg.shared.global [%0], [%1], 16;" :: "r"(sa), "l"(ga));
}
__device__ __forceinline__ void cp_commit() { asm volatile("cp.async.commit_group;"); }
template <int N>
__device__ __forceinline__ void cp_wait() { asm volatile("cp.async.wait_group %0;" :: "n"(N)); }

// ---------------------------------------------------------------------------
// Kernel 0: dtype converts + mask pack
// ---------------------------------------------------------------------------
__global__ void f32_to_f16_kernel(const float* __restrict__ src,
                                  __half* __restrict__ dst, int n4) {
    int i = blockIdx.x * blockDim.x + threadIdx.x;
    if (i < n4) {
        float4 v = ((const float4*)src)[i];
        uint2 u = {pack_h2(v.x, v.y), pack_h2(v.z, v.w)};
        ((uint2*)dst)[i] = u;
    }
}

__global__ void mask_pack_kernel(const int* __restrict__ m) {
    int t = blockIdx.x * blockDim.x + threadIdx.x;
    if (t < T_LEN) {
#pragma unroll
        for (int b = 0; b < BATCH; b++)
            g_mskb[b * T_LEN + t] = (unsigned char)(m[t * BATCH + b] != 0);
    }
}

// ---------------------------------------------------------------------------
// fp16 GEMM core: C[m,n] = sum_k A[m,k] * W[n,k]  (NT). BM=BN=128, BK=64,
// 256 threads, 8 warps 4x2, warp tile 32x64. 2-stage cp.async pipeline.
// ---------------------------------------------------------------------------
#define BK 64
#define HSTR 72   // half stride per row (64 + 8 pad)
#define GEMM_STAGE_HALFS (128 * HSTR)
#define GEMM_SMEM_BYTES (4 * GEMM_STAGE_HALFS * 2)   // A0,A1,B0,B1

__device__ __forceinline__ void gemm_load_stage(__half* As, __half* Bs,
                                                const __half* Ag, const __half* Bg,
                                                int tid) {
#pragma unroll
    for (int i = 0; i < 4; i++) {
        int s = tid + i * 256;       // 1024 chunks of 8 halves per matrix
        int r = s >> 3, c8 = (s & 7) << 3;
        cp16(As + r * HSTR + c8, Ag + (size_t)r * DMODEL + c8);
        cp16(Bs + r * HSTR + c8, Bg + (size_t)r * DMODEL + c8);
    }
}

__device__ __forceinline__ void gemm_mainloop(const __half* smem, const __half* Ag,
                                              const __half* Bg, float acc[2][8][4],
                                              int tid) {
    const int warp = tid >> 5, lane = tid & 31;
    const int wr = warp >> 1, wc = warp & 1;
    const int g = lane >> 2, tig = lane & 3;
    __half* A0 = (__half*)smem;
    __half* B0 = (__half*)smem + 2 * GEMM_STAGE_HALFS;

    gemm_load_stage(A0, B0, Ag, Bg, tid);
    cp_commit();

    for (int kt = 0; kt < 16; kt++) {
        if (kt + 1 < 16) {
            int st = (kt + 1) & 1;
            gemm_load_stage(A0 + st * GEMM_STAGE_HALFS, B0 + st * GEMM_STAGE_HALFS,
                            Ag + (kt + 1) * BK, Bg + (kt + 1) * BK, tid);
            cp_commit();
            cp_wait<1>();
        } else {
            cp_wait<0>();
        }
        __syncthreads();

        const __half (*As)[HSTR] = (const __half (*)[HSTR])(A0 + (kt & 1) * GEMM_STAGE_HALFS);
        const __half (*Bs)[HSTR] = (const __half (*)[HSTR])(B0 + (kt & 1) * GEMM_STAGE_HALFS);
#pragma unroll
        for (int kk = 0; kk < BK; kk += 16) {
            unsigned a[2][4];
#pragma unroll
            for (int mf = 0; mf < 2; mf++) {
                int r0 = wr * 32 + mf * 16;
                a[mf][0] = *(const unsigned*)(&As[r0 + g][kk + 2 * tig]);
                a[mf][1] = *(const unsigned*)(&As[r0 + g + 8][kk + 2 * tig]);
                a[mf][2] = *(const unsigned*)(&As[r0 + g][kk + 2 * tig + 8]);
                a[mf][3] = *(const unsigned*)(&As[r0 + g + 8][kk + 2 * tig + 8]);
            }
#pragma unroll
            for (int nf = 0; nf < 8; nf++) {
                int n0 = wc * 64 + nf * 8;
                unsigned b0 = *(const unsigned*)(&Bs[n0 + g][kk + 2 * tig]);
                unsigned b1 = *(const unsigned*)(&Bs[n0 + g][kk + 2 * tig + 8]);
#pragma unroll
                for (int mf = 0; mf < 2; mf++)
                    mma_f16(acc[mf][nf][0], acc[mf][nf][1], acc[mf][nf][2], acc[mf][nf][3],
                            a[mf][0], a[mf][1], a[mf][2], a[mf][3], b0, b1);
            }
        }
        __syncthreads();
    }
}

// Kernel 1: QKV projection. grid (64, 24): bn<8 -> Q, 8..15 -> K, 16..23 -> V
__global__ __launch_bounds__(256) void qkv_gemm_kernel() {
    extern __shared__ __half smem[];
    const int bm = blockIdx.x, bn = blockIdx.y;
    const int tid = threadIdx.x;
    const int warp = tid >> 5, lane = tid & 31;
    const int wr = warp >> 1, wc = warp & 1;
    const int g = lane >> 2, tig = lane & 3;

    float acc[2][8][4];
#pragma unroll
    for (int i = 0; i < 2; i++)
#pragma unroll
        for (int j = 0; j < 8; j++)
#pragma unroll
            for (int e = 0; e < 4; e++) acc[i][j][e] = 0.f;

    const __half* Ag = g_hh + (size_t)bm * 128 * DMODEL;
    const __half* Bg = g_wqkvh + (size_t)bn * 128 * DMODEL;
    gemm_mainloop(smem, Ag, Bg, acc, tid);

    const int sec = bn >> 3;
    __half* dst = (sec == 0) ? g_Q : ((sec == 1) ? g_K : g_V);
#pragma unroll
    for (int mf = 0; mf < 2; mf++)
#pragma unroll
        for (int nf = 0; nf < 8; nf++)
#pragma unroll
            for (int eh = 0; eh < 2; eh++) {
                int rl = wr * 32 + mf * 16 + g + eh * 8;
                int cl = wc * 64 + nf * 8 + tig * 2;
                int m = bm * 128 + rl;
                int t = m >> 2, b = m & 3;
                int o = (bn & 7) * 128 + cl;
                int head = o >> 6, d = o & 63;
                unsigned pv = pack_h2(acc[mf][nf][eh * 2], acc[mf][nf][eh * 2 + 1]);
                *(unsigned*)(&dst[(((size_t)(b * NHEAD + head) * T_LEN + t) << 6) + d]) = pv;
            }
}

// Kernel 3a: out projection + residual. grid (64, 8).
__global__ __launch_bounds__(256) void outproj_gemm_kernel(const float* __restrict__ hmat) {
    extern __shared__ __half smem[];
    const int bm = blockIdx.x, bn = blockIdx.y;
    const int tid = threadIdx.x;
    const int warp = tid >> 5, lane = tid & 31;
    const int wr = warp >> 1, wc = warp & 1;
    const int g = lane >> 2, tig = lane & 3;

    float acc[2][8][4];
#pragma unroll
    for (int i = 0; i < 2; i++)
#pragma unroll
        for (int j = 0; j < 8; j++)
#pragma unroll
            for (int e = 0; e < 4; e++) acc[i][j][e] = 0.f;

    const __half* Ag = g_att + (size_t)bm * 128 * DMODEL;
    const __half* Bg = g_woh + (size_t)bn * 128 * DMODEL;
    gemm_mainloop(smem, Ag, Bg, acc, tid);

#pragma unroll
    for (int mf = 0; mf < 2; mf++)
#pragma unroll
        for (int nf = 0; nf < 8; nf++)
#pragma unroll
            for (int e = 0; e < 4; e++) {
                int rl = wr * 32 + mf * 16 + g + ((e >= 2) ? 8 : 0);
                int cl = wc * 64 + nf * 8 + tig * 2 + (e & 1);
                int m = bm * 128 + rl;
                int col = bn * 128 + cl;
                size_t idx = (size_t)m * DMODEL + col;
                g_res[idx] = acc[mf][nf][e] + hmat[idx];
            }
}

// ---------------------------------------------------------------------------
// Kernel 2: flash attention, fp16, P-in-register, cp.async K/V/mask pipeline.
// grid (16 qblocks, 64 bh). 256 threads, 2 CTAs/SM.
// ---------------------------------------------------------------------------
#define KV_STAGE_HALFS (128 * HSTR)
#define FLASH_Q_OFF 0
#define FLASH_K_OFF (128 * HSTR)
#define FLASH_V_OFF (FLASH_K_OFF + 2 * KV_STAGE_HALFS)
#define FLASH_MSK_OFF (FLASH_V_OFF + 2 * KV_STAGE_HALFS)   // in halves
#define FLASH_SMEM_BYTES (FLASH_MSK_OFF * 2 + 2 * 128 + 256)

__device__ __forceinline__ void flash_load_kv(__half* Kdst, __half* Vdst,
                                              const __half* Kg, const __half* Vg,
                                              int tid) {
#pragma unroll
    for (int i = 0; i < 4; i++) {
        int s = tid + i * 256;        // 1024 chunks of 8 halves per matrix
        int r = s >> 3, c8 = (s & 7) << 3;
        cp16(Kdst + r * HSTR + c8, Kg + (size_t)r * DHEAD + c8);
        cp16(Vdst + r * HSTR + c8, Vg + (size_t)r * DHEAD + c8);
    }
}

__global__ __launch_bounds__(256, 2) void flash_attn_kernel() {
    extern __shared__ __half sm[];
    __half (*Qs)[HSTR] = (__half (*)[HSTR])(sm + FLASH_Q_OFF);
    __half* Kbase = sm + FLASH_K_OFF;
    __half* Vbase = sm + FLASH_V_OFF;
    unsigned char* mbase = (unsigned char*)(sm + FLASH_MSK_OFF);

    const int qb = blockIdx.x, bh = blockIdx.y;
    const int b = bh >> 4, hh = bh & 15;
    const int tid = threadIdx.x;
    const int warp = tid >> 5, lane = tid & 31;
    const int g = lane >> 2, tig = lane & 3;
    const int row0 = warp * 16;

    const __half* Qg = g_Q + (size_t)bh * T_LEN * DHEAD + (size_t)qb * 128 * DHEAD;
    const __half* Kg = g_K + (size_t)bh * T_LEN * DHEAD;
    const __half* Vg = g_V + (size_t)bh * T_LEN * DHEAD;
    const unsigned char* Mg = g_mskb + (size_t)b * T_LEN;

    // Load Q tile (128x64 half) via plain stores
#pragma unroll
    for (int i = 0; i < 4; i++) {
        int s = tid + i * 256;
        int r = s >> 3, c8 = (s & 7) << 3;
        uint4 u = *(const uint4*)(Qg + (size_t)r * DHEAD + c8);
        *(uint4*)(&Qs[r][c8]) = u;
    }

    // prologue: stage 0 of K/V/mask
    flash_load_kv(Kbase, Vbase, Kg, Vg, tid);
    if (tid < 8) cp16(mbase + tid * 16, Mg + tid * 16);
    cp_commit();

    float m_i[2] = {NEG_INF, NEG_INF};
    float l_i[2] = {0.f, 0.f};
    float o_acc[8][4];
#pragma unroll
    for (int nf = 0; nf < 8; nf++)
#pragma unroll
        for (int e = 0; e < 4; e++) o_acc[nf][e] = 0.f;

    for (int kb = 0; kb < 16; kb++) {
        if (kb + 1 < 16) {
            int st = (kb + 1) & 1;
            flash_load_kv(Kbase + st * KV_STAGE_HALFS, Vbase + st * KV_STAGE_HALFS,
                          Kg + (size_t)(kb + 1) * 128 * DHEAD,
                          Vg + (size_t)(kb + 1) * 128 * DHEAD, tid);
            if (tid < 8) cp16(mbase + st * 128 + tid * 16, Mg + (kb + 1) * 128 + tid * 16);
            cp_commit();
            cp_wait<1>();
        } else {
            cp_wait<0>();
        }
        __syncthreads();

        const int st = kb & 1;
        const __half (*Ks)[HSTR] = (const __half (*)[HSTR])(Kbase + st * KV_STAGE_HALFS);
        const __half (*Vs)[HSTR] = (const __half (*)[HSTR])(Vbase + st * KV_STAGE_HALFS);
        const unsigned char* msk = mbase + st * 128;

        // S = Q @ K^T  (warp: 16 rows x 128 cols), 4 k16 steps over d=64
        float s_acc[16][4];
#pragma unroll
        for (int nf = 0; nf < 16; nf++)
#pragma unroll
            for (int e = 0; e < 4; e++) s_acc[nf][e] = 0.f;
#pragma unroll
        for (int kk = 0; kk < 64; kk += 16) {
            unsigned a0 = *(const unsigned*)(&Qs[row0 + g][kk + 2 * tig]);
            unsigned a1 = *(const unsigned*)(&Qs[row0 + g + 8][kk + 2 * tig]);
            unsigned a2 = *(const unsigned*)(&Qs[row0 + g][kk + 2 * tig + 8]);
            unsigned a3 = *(const unsigned*)(&Qs[row0 + g + 8][kk + 2 * tig + 8]);
#pragma unroll
            for (int nf = 0; nf < 16; nf++) {
                unsigned b0 = *(const unsigned*)(&Ks[nf * 8 + g][kk + 2 * tig]);
                unsigned b1 = *(const unsigned*)(&Ks[nf * 8 + g][kk + 2 * tig + 8]);
                mma_f16(s_acc[nf][0], s_acc[nf][1], s_acc[nf][2], s_acc[nf][3],
                        a0, a1, a2, a3, b0, b1);
            }
        }

        // scale + mask + row max
        float mx[2] = {NEG_INF, NEG_INF};
#pragma unroll
        for (int nf = 0; nf < 16; nf++) {
            int c0 = nf * 8 + tig * 2;
            bool k0m = msk[c0] != 0, k1m = msk[c0 + 1] != 0;
            s_acc[nf][0] = k0m ? NEG_INF : s_acc[nf][0] * SCALE_ATT;
            s_acc[nf][1] = k1m ? NEG_INF : s_acc[nf][1] * SCALE_ATT;
            s_acc[nf][2] = k0m ? NEG_INF : s_acc[nf][2] * SCALE_ATT;
            s_acc[nf][3] = k1m ? NEG_INF : s_acc[nf][3] * SCALE_ATT;
            mx[0] = fmaxf(mx[0], fmaxf(s_acc[nf][0], s_acc[nf][1]));
            mx[1] = fmaxf(mx[1], fmaxf(s_acc[nf][2], s_acc[nf][3]));
        }
#pragma unroll
        for (int off = 1; off < 4; off <<= 1) {
            mx[0] = fmaxf(mx[0], __shfl_xor_sync(0xffffffffu, mx[0], off));
            mx[1] = fmaxf(mx[1], __shfl_xor_sync(0xffffffffu, mx[1], off));
        }

        float alpha[2], mc[2];
#pragma unroll
        for (int r = 0; r < 2; r++) {
            float mnew = fmaxf(m_i[r], mx[r]);
            alpha[r] = __expf(clamp_m(m_i[r]) - clamp_m(mnew));
            m_i[r] = mnew;
            mc[r] = clamp_m(mnew);
        }

        // p = exp(s - m); pack P directly into A-fragments (no smem roundtrip):
        // accumulator (c0,c1)@row g == A-frag (a0|a2); (c2,c3)@row g+8 == (a1|a3)
        unsigned pA[16][2];
        float ps[2] = {0.f, 0.f};
#pragma unroll
        for (int nf = 0; nf < 16; nf++) {
            float p0 = __expf(s_acc[nf][0] - mc[0]);
            float p1 = __expf(s_acc[nf][1] - mc[0]);
            float p2 = __expf(s_acc[nf][2] - mc[1]);
            float p3 = __expf(s_acc[nf][3] - mc[1]);
            ps[0] += p0 + p1;
            ps[1] += p2 + p3;
            pA[nf][0] = pack_h2(p0, p1);
            pA[nf][1] = pack_h2(p2, p3);
        }
#pragma unroll
        for (int off = 1; off < 4; off <<= 1) {
            ps[0] += __shfl_xor_sync(0xffffffffu, ps[0], off);
            ps[1] += __shfl_xor_sync(0xffffffffu, ps[1], off);
        }
        l_i[0] = l_i[0] * alpha[0] + ps[0];
        l_i[1] = l_i[1] * alpha[1] + ps[1];

#pragma unroll
        for (int nf = 0; nf < 8; nf++) {
            o_acc[nf][0] *= alpha[0];
            o_acc[nf][1] *= alpha[0];
            o_acc[nf][2] *= alpha[1];
            o_acc[nf][3] *= alpha[1];
        }

        // O += P @ V : 8 k16 steps; A-frags from registers, V via ldmatrix.trans
#pragma unroll
        for (int j = 0; j < 8; j++) {
            int kk = j * 16;
            unsigned a0 = pA[2 * j][0];
            unsigned a1 = pA[2 * j][1];
            unsigned a2 = pA[2 * j + 1][0];
            unsigned a3 = pA[2 * j + 1][1];
#pragma unroll
            for (int nfp = 0; nfp < 4; nfp++) {
                int mt = lane >> 3, ri = lane & 7;
                const __half* vp = &Vs[kk + ri + ((mt & 1) << 3)][nfp * 16 + ((mt >> 1) << 3)];
                unsigned r0, r1, r2, r3;
                ldsm_x4_trans(r0, r1, r2, r3, vp);
                int nf = nfp * 2;
                mma_f16(o_acc[nf][0], o_acc[nf][1], o_acc[nf][2], o_acc[nf][3],
                        a0, a1, a2, a3, r0, r1);
                mma_f16(o_acc[nf + 1][0], o_acc[nf + 1][1], o_acc[nf + 1][2], o_acc[nf + 1][3],
                        a0, a1, a2, a3, r2, r3);
            }
        }
        __syncthreads();
    }

    float inv_l[2] = {1.f / l_i[0], 1.f / l_i[1]};
#pragma unroll
    for (int nf = 0; nf < 8; nf++)
#pragma unroll
        for (int eh = 0; eh < 2; eh++) {
            int t = qb * 128 + row0 + g + eh * 8;
            int d = nf * 8 + tig * 2;
            int m = t * BATCH + b;
            unsigned pv = pack_h2(o_acc[nf][eh * 2] * inv_l[eh],
                                  o_acc[nf][eh * 2 + 1] * inv_l[eh]);
            *(unsigned*)(&g_att[(size_t)m * DMODEL + hh * DHEAD + d]) = pv;
        }
}

// ---------------------------------------------------------------------------
// Kernel 3b: LayerNorm per row (1024 elems), two-pass, register-resident.
// ---------------------------------------------------------------------------
__device__ __forceinline__ float block_sum256(float v) {
    __shared__ float red[8];
#pragma unroll
    for (int off = 16; off > 0; off >>= 1) v += __shfl_xor_sync(0xffffffffu, v, off);
    if ((threadIdx.x & 31) == 0) red[threadIdx.x >> 5] = v;
    __syncthreads();
    v = red[0] + red[1] + red[2] + red[3] + red[4] + red[5] + red[6] + red[7];
    __syncthreads();
    return v;
}

__global__ __launch_bounds__(256) void layernorm_kernel(
    const float* __restrict__ lng, const float* __restrict__ lnb,
    float* __restrict__ out)
{
    const int row = blockIdx.x;
    const int tid = threadIdx.x;
    const float* x = g_res + (size_t)row * DMODEL;
    float4 v = *(const float4*)(x + tid * 4);
    float s = block_sum256(v.x + v.y + v.z + v.w);
    float mu = s * (1.f / DMODEL);
    float dx = v.x - mu, dy = v.y - mu, dz = v.z - mu, dw = v.w - mu;
    float sq = block_sum256(dx * dx + dy * dy + dz * dz + dw * dw);
    float var = sq * (1.f / DMODEL);
    float rstd = rsqrtf(var + 1e-5f);
    float4 gg = *(const float4*)(lng + tid * 4);
    float4 bb = *(const float4*)(lnb + tid * 4);
    float4 r;
    r.x = dx * rstd * gg.x + bb.x;
    r.y = dy * rstd * gg.y + bb.y;
    r.z = dz * rstd * gg.z + bb.z;
    r.w = dw * rstd * gg.w + bb.w;
    *(float4*)(out + (size_t)row * DMODEL + tid * 4) = r;
}

// ---------------------------------------------------------------------------
extern "C" void kernel_launch(void* const* d_in, const int* in_sizes, int n_in,
                              void* d_out, int out_size) {
    const float* h = (const float*)d_in[0];
    const int* mask = (const int*)d_in[1];
    const float* wq = (const float*)d_in[2];
    const float* wkv = (const float*)d_in[3];
    const float* wo = (const float*)d_in[4];
    const float* lng = (const float*)d_in[5];
    const float* lnb = (const float*)d_in[6];
    float* out = (float*)d_out;

    cudaFuncSetAttribute(flash_attn_kernel,
                         cudaFuncAttributeMaxDynamicSharedMemorySize, FLASH_SMEM_BYTES);
    cudaFuncSetAttribute(qkv_gemm_kernel,
                         cudaFuncAttributeMaxDynamicSharedMemorySize, GEMM_SMEM_BYTES);
    cudaFuncSetAttribute(outproj_gemm_kernel,
                         cudaFuncAttributeMaxDynamicSharedMemorySize, GEMM_SMEM_BYTES);

    __half* d_hh;    cudaGetSymbolAddress((void**)&d_hh, g_hh);
    __half* d_wqkvh; cudaGetSymbolAddress((void**)&d_wqkvh, g_wqkvh);
    __half* d_woh;   cudaGetSymbolAddress((void**)&d_woh, g_woh);

    // dtype converts (fp32 -> fp16) + mask pack
    f32_to_f16_kernel<<<(MROWS * DMODEL / 4 + 255) / 256, 256>>>(h, d_hh, MROWS * DMODEL / 4);
    f32_to_f16_kernel<<<(1024 * DMODEL / 4 + 255) / 256, 256>>>(wq, d_wqkvh, 1024 * DMODEL / 4);
    f32_to_f16_kernel<<<(2048 * DMODEL / 4 + 255) / 256, 256>>>(wkv, d_wqkvh + 1024 * DMODEL,
                                                                2048 * DMODEL / 4);
    f32_to_f16_kernel<<<(DMODEL * DMODEL / 4 + 255) / 256, 256>>>(wo, d_woh, DMODEL * DMODEL / 4);
    mask_pack_kernel<<<(T_LEN + 255) / 256, 256>>>(mask);

    qkv_gemm_kernel<<<dim3(64, 24), 256, GEMM_SMEM_BYTES>>>();
    flash_attn_kernel<<<dim3(16, 64), 256, FLASH_SMEM_BYTES>>>();
    outproj_gemm_kernel<<<dim3(64, 8), 256, GEMM_SMEM_BYTES>>>(h);
    layernorm_kernel<<<MROWS, 256>>>(lng, lnb, out);
}

// round 6
// speedup vs baseline: 2.7150x; 1.1065x over previous
#include <cuda_runtime.h>
#include <cuda_fp16.h>
#include <cstdint>

// ---------------------------------------------------------------------------
// MultiHeadAttn: T=2048, B=4, N_HEAD=16, D_HEAD=64, D_MODEL=1024
// Round 6: ldmatrix fragment loads, spill-free flash (64-key chunks, hoisted
// Q frags), log2-domain softmax with additive float mask, fused prep kernel.
// ---------------------------------------------------------------------------

#define T_LEN 2048
#define BATCH 4
#define NHEAD 16
#define DHEAD 64
#define DMODEL 1024
#define MROWS (T_LEN * BATCH)        // 8192
#define QSCALE_LOG2E 0.180336878f    // (1/sqrt(64)) * log2(e)
#define MASKF -1e38f

// Scratch (static device globals; no runtime allocation)
__device__ __half g_hh[MROWS * DMODEL];
__device__ __half g_wqkvh[3072 * DMODEL];
__device__ __half g_woh[DMODEL * DMODEL];
__device__ float  g_mskf[BATCH * T_LEN];                // 0 or -1e38, [b][t]
__device__ __half g_Q[BATCH * NHEAD * T_LEN * DHEAD];   // [bh][t][d] (pre-scaled? no: raw)
__device__ __half g_K[BATCH * NHEAD * T_LEN * DHEAD];
__device__ __half g_V[BATCH * NHEAD * T_LEN * DHEAD];
__device__ __half g_att[MROWS * DMODEL];
__device__ float  g_res[MROWS * DMODEL];

#define NEG_INF __int_as_float(0xff800000)

__device__ __forceinline__ float clamp_m(float x) { return fmaxf(x, -1e30f); }

__device__ __forceinline__ float ex2(float x) {
    float r;
    asm("ex2.approx.ftz.f32 %0, %1;" : "=f"(r) : "f"(x));
    return r;
}

__device__ __forceinline__ void mma_f16(float& c0, float& c1, float& c2, float& c3,
                                        unsigned a0, unsigned a1, unsigned a2, unsigned a3,
                                        unsigned b0, unsigned b1) {
    asm volatile(
        "mma.sync.aligned.m16n8k16.row.col.f32.f16.f16.f32 "
        "{%0,%1,%2,%3},{%4,%5,%6,%7},{%8,%9},{%0,%1,%2,%3};"
        : "+f"(c0), "+f"(c1), "+f"(c2), "+f"(c3)
        : "r"(a0), "r"(a1), "r"(a2), "r"(a3), "r"(b0), "r"(b1));
}

__device__ __forceinline__ void ldsm_x4(unsigned& r0, unsigned& r1,
                                        unsigned& r2, unsigned& r3,
                                        const __half* p) {
    unsigned sa = (unsigned)__cvta_generic_to_shared(p);
    asm volatile("ldmatrix.sync.aligned.m8n8.x4.shared.b16 {%0,%1,%2,%3}, [%4];"
                 : "=r"(r0), "=r"(r1), "=r"(r2), "=r"(r3) : "r"(sa));
}

__device__ __forceinline__ void ldsm_x4_trans(unsigned& r0, unsigned& r1,
                                              unsigned& r2, unsigned& r3,
                                              const __half* p) {
    unsigned sa = (unsigned)__cvta_generic_to_shared(p);
    asm volatile("ldmatrix.sync.aligned.m8n8.x4.trans.shared.b16 {%0,%1,%2,%3}, [%4];"
                 : "=r"(r0), "=r"(r1), "=r"(r2), "=r"(r3) : "r"(sa));
}

__device__ __forceinline__ unsigned pack_h2(float a, float b) {
    __half2 h = __floats2half2_rn(a, b);
    return *(unsigned*)&h;
}

__device__ __forceinline__ void cp16(const void* smem_dst, const void* gsrc) {
    unsigned sa = (unsigned)__cvta_generic_to_shared(smem_dst);
    unsigned long long ga = (unsigned long long)__cvta_generic_to_global(gsrc);
    asm volatile("cp.async.cg.shared.global [%0], [%1], 16;" :: "r"(sa), "l"(ga));
}
__device__ __forceinline__ void cp_commit() { asm volatile("cp.async.commit_group;"); }
template <int N>
__device__ __forceinline__ void cp_wait() { asm volatile("cp.async.wait_group %0;" :: "n"(N)); }

// ---------------------------------------------------------------------------
// Kernel 0: fused dtype converts + mask->float pack
// ---------------------------------------------------------------------------
#define H4   (MROWS * DMODEL / 4)      // 2097152
#define WQ4  (1024 * DMODEL / 4)       // 262144
#define WKV4 (2048 * DMODEL / 4)       // 524288
#define WO4  (DMODEL * DMODEL / 4)     // 262144
#define TOT4 (H4 + WQ4 + WKV4 + WO4)   // 3145728

__global__ __launch_bounds__(256) void conv_all_kernel(
    const float* __restrict__ h, const float* __restrict__ wq,
    const float* __restrict__ wkv, const float* __restrict__ wo,
    const int* __restrict__ mask)
{
    int i = blockIdx.x * 256 + threadIdx.x;
    if (i < TOT4) {
        const float* src;
        __half* dst;
        int off;
        if (i < H4) { src = h; dst = g_hh; off = i; }
        else if (i < H4 + WQ4) { src = wq; dst = g_wqkvh; off = i - H4; }
        else if (i < H4 + WQ4 + WKV4) { src = wkv; dst = g_wqkvh + 1024 * DMODEL / 4 * 4; off = i - H4 - WQ4; }
        else { src = wo; dst = g_woh; off = i - H4 - WQ4 - WKV4; }
        float4 v = ((const float4*)src)[off];
        uint2 u = {pack_h2(v.x, v.y), pack_h2(v.z, v.w)};
        ((uint2*)dst)[off] = u;
    } else {
        int t = i - TOT4;
        if (t < T_LEN) {
#pragma unroll
            for (int b = 0; b < BATCH; b++)
                g_mskf[b * T_LEN + t] = (mask[t * BATCH + b] != 0) ? MASKF : 0.f;
        }
    }
}

// ---------------------------------------------------------------------------
// fp16 GEMM core with ldmatrix fragments. BM=BN=128, BK=64, 8 warps 4x2.
// ---------------------------------------------------------------------------
#define BK 64
#define HSTR 72   // half stride per row (64 + 8 pad) -> LDSM conflict-free
#define GEMM_STAGE_HALFS (128 * HSTR)
#define GEMM_SMEM_BYTES (4 * GEMM_STAGE_HALFS * 2)   // A0,A1,B0,B1

__device__ __forceinline__ void gemm_load_stage(__half* As, __half* Bs,
                                                const __half* Ag, const __half* Bg,
                                                int tid) {
#pragma unroll
    for (int i = 0; i < 4; i++) {
        int s = tid + i * 256;
        int r = s >> 3, c8 = (s & 7) << 3;
        cp16(As + r * HSTR + c8, Ag + (size_t)r * DMODEL + c8);
        cp16(Bs + r * HSTR + c8, Bg + (size_t)r * DMODEL + c8);
    }
}

__device__ __forceinline__ void gemm_mainloop(const __half* smem, const __half* Ag,
                                              const __half* Bg, float acc[2][8][4],
                                              int tid) {
    const int warp = tid >> 5, lane = tid & 31;
    const int wr = warp >> 1, wc = warp & 1;
    const int lrow = lane & 15, lcol = (lane >> 4) << 3;
    __half* A0 = (__half*)smem;
    __half* B0 = (__half*)smem + 2 * GEMM_STAGE_HALFS;

    gemm_load_stage(A0, B0, Ag, Bg, tid);
    cp_commit();

    for (int kt = 0; kt < 16; kt++) {
        if (kt + 1 < 16) {
            int st = (kt + 1) & 1;
            gemm_load_stage(A0 + st * GEMM_STAGE_HALFS, B0 + st * GEMM_STAGE_HALFS,
                            Ag + (kt + 1) * BK, Bg + (kt + 1) * BK, tid);
            cp_commit();
            cp_wait<1>();
        } else {
            cp_wait<0>();
        }
        __syncthreads();

        const __half (*As)[HSTR] = (const __half (*)[HSTR])(A0 + (kt & 1) * GEMM_STAGE_HALFS);
        const __half (*Bs)[HSTR] = (const __half (*)[HSTR])(B0 + (kt & 1) * GEMM_STAGE_HALFS);
#pragma unroll
        for (int kk = 0; kk < BK; kk += 16) {
            unsigned a[2][4];
#pragma unroll
            for (int mf = 0; mf < 2; mf++)
                ldsm_x4(a[mf][0], a[mf][1], a[mf][2], a[mf][3],
                        &As[wr * 32 + mf * 16 + lrow][kk + lcol]);
#pragma unroll
            for (int np = 0; np < 4; np++) {
                unsigned b0, b1, b2, b3;   // b0/b2 -> nf=2np; b1/b3 -> nf=2np+1
                ldsm_x4(b0, b1, b2, b3, &Bs[wc * 64 + np * 16 + lrow][kk + lcol]);
#pragma unroll
                for (int mf = 0; mf < 2; mf++) {
                    mma_f16(acc[mf][2 * np][0], acc[mf][2 * np][1],
                            acc[mf][2 * np][2], acc[mf][2 * np][3],
                            a[mf][0], a[mf][1], a[mf][2], a[mf][3], b0, b2);
                    mma_f16(acc[mf][2 * np + 1][0], acc[mf][2 * np + 1][1],
                            acc[mf][2 * np + 1][2], acc[mf][2 * np + 1][3],
                            a[mf][0], a[mf][1], a[mf][2], a[mf][3], b1, b3);
                }
            }
        }
        __syncthreads();
    }
}

// Kernel 1: QKV projection. grid (64, 24): bn<8 -> Q, 8..15 -> K, 16..23 -> V
__global__ __launch_bounds__(256, 2) void qkv_gemm_kernel() {
    extern __shared__ __half smem[];
    const int bm = blockIdx.x, bn = blockIdx.y;
    const int tid = threadIdx.x;
    const int warp = tid >> 5, lane = tid & 31;
    const int wr = warp >> 1, wc = warp & 1;
    const int g = lane >> 2, tig = lane & 3;

    float acc[2][8][4];
#pragma unroll
    for (int i = 0; i < 2; i++)
#pragma unroll
        for (int j = 0; j < 8; j++)
#pragma unroll
            for (int e = 0; e < 4; e++) acc[i][j][e] = 0.f;

    gemm_mainloop(smem, g_hh + (size_t)bm * 128 * DMODEL,
                  g_wqkvh + (size_t)bn * 128 * DMODEL, acc, tid);

    const int sec = bn >> 3;
    __half* dst = (sec == 0) ? g_Q : ((sec == 1) ? g_K : g_V);
#pragma unroll
    for (int mf = 0; mf < 2; mf++)
#pragma unroll
        for (int nf = 0; nf < 8; nf++)
#pragma unroll
            for (int eh = 0; eh < 2; eh++) {
                int rl = wr * 32 + mf * 16 + g + eh * 8;
                int cl = wc * 64 + nf * 8 + tig * 2;
                int m = bm * 128 + rl;
                int t = m >> 2, b = m & 3;
                int o = (bn & 7) * 128 + cl;
                int head = o >> 6, d = o & 63;
                unsigned pv = pack_h2(acc[mf][nf][eh * 2], acc[mf][nf][eh * 2 + 1]);
                *(unsigned*)(&dst[(((size_t)(b * NHEAD + head) * T_LEN + t) << 6) + d]) = pv;
            }
}

// Kernel 3a: out projection + residual. grid (64, 8).
__global__ __launch_bounds__(256, 2) void outproj_gemm_kernel(const float* __restrict__ hmat) {
    extern __shared__ __half smem[];
    const int bm = blockIdx.x, bn = blockIdx.y;
    const int tid = threadIdx.x;
    const int warp = tid >> 5, lane = tid & 31;
    const int wr = warp >> 1, wc = warp & 1;
    const int g = lane >> 2, tig = lane & 3;

    float acc[2][8][4];
#pragma unroll
    for (int i = 0; i < 2; i++)
#pragma unroll
        for (int j = 0; j < 8; j++)
#pragma unroll
            for (int e = 0; e < 4; e++) acc[i][j][e] = 0.f;

    gemm_mainloop(smem, g_att + (size_t)bm * 128 * DMODEL,
                  g_woh + (size_t)bn * 128 * DMODEL, acc, tid);

#pragma unroll
    for (int mf = 0; mf < 2; mf++)
#pragma unroll
        for (int nf = 0; nf < 8; nf++)
#pragma unroll
            for (int e = 0; e < 4; e++) {
                int rl = wr * 32 + mf * 16 + g + ((e >= 2) ? 8 : 0);
                int cl = wc * 64 + nf * 8 + tig * 2 + (e & 1);
                int m = bm * 128 + rl;
                int col = bn * 128 + cl;
                size_t idx = (size_t)m * DMODEL + col;
                g_res[idx] = acc[mf][nf][e] + hmat[idx];
            }
}

// ---------------------------------------------------------------------------
// Kernel 2: flash attention. 64-key chunks (spill-free), hoisted Q frags,
// log2-domain softmax, additive float mask, cp.async K/V/mask pipeline.
// grid (16 qblocks, 64 bh). 256 threads, 2 CTAs/SM.
// ---------------------------------------------------------------------------
#define KV_STAGE_HALFS (128 * HSTR)
#define FLASH_Q_OFF 0
#define FLASH_K_OFF (128 * HSTR)
#define FLASH_V_OFF (FLASH_K_OFF + 2 * KV_STAGE_HALFS)
#define FLASH_MSK_OFF (FLASH_V_OFF + 2 * KV_STAGE_HALFS)   // halves; 2 stages x 128 floats
#define FLASH_SMEM_BYTES (FLASH_MSK_OFF * 2 + 2 * 128 * 4 + 256)

__device__ __forceinline__ void flash_load_kv(__half* Kdst, __half* Vdst,
                                              const __half* Kg, const __half* Vg,
                                              int tid) {
#pragma unroll
    for (int i = 0; i < 4; i++) {
        int s = tid + i * 256;
        int r = s >> 3, c8 = (s & 7) << 3;
        cp16(Kdst + r * HSTR + c8, Kg + (size_t)r * DHEAD + c8);
        cp16(Vdst + r * HSTR + c8, Vg + (size_t)r * DHEAD + c8);
    }
}

__global__ __launch_bounds__(256, 2) void flash_attn_kernel() {
    extern __shared__ __half sm[];
    __half (*Qs)[HSTR] = (__half (*)[HSTR])(sm + FLASH_Q_OFF);
    __half* Kbase = sm + FLASH_K_OFF;
    __half* Vbase = sm + FLASH_V_OFF;
    float* mfbase = (float*)(sm + FLASH_MSK_OFF);

    const int qb = blockIdx.x, bh = blockIdx.y;
    const int b = bh >> 4, hh = bh & 15;
    const int tid = threadIdx.x;
    const int warp = tid >> 5, lane = tid & 31;
    const int g = lane >> 2, tig = lane & 3;
    const int lrow = lane & 15, lcol = (lane >> 4) << 3;
    const int row0 = warp * 16;

    const __half* Qg = g_Q + (size_t)bh * T_LEN * DHEAD + (size_t)qb * 128 * DHEAD;
    const __half* Kg = g_K + (size_t)bh * T_LEN * DHEAD;
    const __half* Vg = g_V + (size_t)bh * T_LEN * DHEAD;
    const float* Mg = g_mskf + (size_t)b * T_LEN;

    // Stage 0 of K/V/mask first (get loads in flight)
    flash_load_kv(Kbase, Vbase, Kg, Vg, tid);
    if (tid < 32) cp16(mfbase + tid * 4, Mg + tid * 4);
    cp_commit();

    // Load Q tile pre-scaled by SCALE*log2e
    const __half2 qs2 = __float2half2_rn(QSCALE_LOG2E);
#pragma unroll
    for (int i = 0; i < 4; i++) {
        int s = tid + i * 256;
        int r = s >> 3, c8 = (s & 7) << 3;
        uint4 u = *(const uint4*)(Qg + (size_t)r * DHEAD + c8);
        __half2* hp = (__half2*)&u;
#pragma unroll
        for (int q = 0; q < 4; q++) hp[q] = __hmul2(hp[q], qs2);
        *(uint4*)(&Qs[r][c8]) = u;
    }
    __syncthreads();

    // Hoist Q fragments (invariant across all k-blocks)
    unsigned qf[4][4];
#pragma unroll
    for (int kk = 0; kk < 4; kk++)
        ldsm_x4(qf[kk][0], qf[kk][1], qf[kk][2], qf[kk][3],
                &Qs[row0 + lrow][kk * 16 + lcol]);

    float m_i[2] = {NEG_INF, NEG_INF};
    float l_i[2] = {0.f, 0.f};
    float o_acc[8][4];
#pragma unroll
    for (int nf = 0; nf < 8; nf++)
#pragma unroll
        for (int e = 0; e < 4; e++) o_acc[nf][e] = 0.f;

    for (int kb = 0; kb < 16; kb++) {
        if (kb + 1 < 16) {
            int st = (kb + 1) & 1;
            flash_load_kv(Kbase + st * KV_STAGE_HALFS, Vbase + st * KV_STAGE_HALFS,
                          Kg + (size_t)(kb + 1) * 128 * DHEAD,
                          Vg + (size_t)(kb + 1) * 128 * DHEAD, tid);
            if (tid < 32) cp16(mfbase + st * 128 + tid * 4, Mg + (kb + 1) * 128 + tid * 4);
            cp_commit();
            cp_wait<1>();
        } else {
            cp_wait<0>();
        }
        __syncthreads();

        const int st = kb & 1;
        const __half (*Ks)[HSTR] = (const __half (*)[HSTR])(Kbase + st * KV_STAGE_HALFS);
        const __half (*Vs)[HSTR] = (const __half (*)[HSTR])(Vbase + st * KV_STAGE_HALFS);
        const float* mskf = mfbase + st * 128;

#pragma unroll
        for (int half = 0; half < 2; half++) {
            const int base = half * 64;

            // S = Q @ K^T for 64 keys (8 nf), already in log2 units
            float s_acc[8][4];
#pragma unroll
            for (int nf = 0; nf < 8; nf++)
#pragma unroll
                for (int e = 0; e < 4; e++) s_acc[nf][e] = 0.f;
#pragma unroll
            for (int kk = 0; kk < 4; kk++) {
#pragma unroll
                for (int np = 0; np < 4; np++) {
                    unsigned b0, b1, b2, b3;
                    ldsm_x4(b0, b1, b2, b3,
                            &Ks[base + np * 16 + lrow][kk * 16 + lcol]);
                    mma_f16(s_acc[2 * np][0], s_acc[2 * np][1],
                            s_acc[2 * np][2], s_acc[2 * np][3],
                            qf[kk][0], qf[kk][1], qf[kk][2], qf[kk][3], b0, b2);
                    mma_f16(s_acc[2 * np + 1][0], s_acc[2 * np + 1][1],
                            s_acc[2 * np + 1][2], s_acc[2 * np + 1][3],
                            qf[kk][0], qf[kk][1], qf[kk][2], qf[kk][3], b1, b3);
                }
            }

            // additive mask + row max
            float mx[2] = {NEG_INF, NEG_INF};
#pragma unroll
            for (int nf = 0; nf < 8; nf++) {
                int c0 = base + nf * 8 + tig * 2;
                float2 mm = *(const float2*)(&mskf[c0]);
                s_acc[nf][0] += mm.x;
                s_acc[nf][1] += mm.y;
                s_acc[nf][2] += mm.x;
                s_acc[nf][3] += mm.y;
                mx[0] = fmaxf(mx[0], fmaxf(s_acc[nf][0], s_acc[nf][1]));
                mx[1] = fmaxf(mx[1], fmaxf(s_acc[nf][2], s_acc[nf][3]));
            }
#pragma unroll
            for (int off = 1; off < 4; off <<= 1) {
                mx[0] = fmaxf(mx[0], __shfl_xor_sync(0xffffffffu, mx[0], off));
                mx[1] = fmaxf(mx[1], __shfl_xor_sync(0xffffffffu, mx[1], off));
            }

            float alpha[2], mc[2];
#pragma unroll
            for (int r = 0; r < 2; r++) {
                float mnew = fmaxf(m_i[r], mx[r]);
                alpha[r] = ex2(clamp_m(m_i[r]) - clamp_m(mnew));
                m_i[r] = mnew;
                mc[r] = clamp_m(mnew);
            }

            // p = 2^(s-m); pack into A-fragments (acc layout == A-frag layout)
            unsigned pA[8][2];
            float ps[2] = {0.f, 0.f};
#pragma unroll
            for (int nf = 0; nf < 8; nf++) {
                float p0 = ex2(s_acc[nf][0] - mc[0]);
                float p1 = ex2(s_acc[nf][1] - mc[0]);
                float p2 = ex2(s_acc[nf][2] - mc[1]);
                float p3 = ex2(s_acc[nf][3] - mc[1]);
                ps[0] += p0 + p1;
                ps[1] += p2 + p3;
                pA[nf][0] = pack_h2(p0, p1);
                pA[nf][1] = pack_h2(p2, p3);
            }
#pragma unroll
            for (int off = 1; off < 4; off <<= 1) {
                ps[0] += __shfl_xor_sync(0xffffffffu, ps[0], off);
                ps[1] += __shfl_xor_sync(0xffffffffu, ps[1], off);
            }
            l_i[0] = l_i[0] * alpha[0] + ps[0];
            l_i[1] = l_i[1] * alpha[1] + ps[1];

#pragma unroll
            for (int nf = 0; nf < 8; nf++) {
                o_acc[nf][0] *= alpha[0];
                o_acc[nf][1] *= alpha[0];
                o_acc[nf][2] *= alpha[1];
                o_acc[nf][3] *= alpha[1];
            }

            // O += P @ V over these 64 keys; V frags via ldmatrix.trans
#pragma unroll
            for (int j = 0; j < 4; j++) {
                int kk = base + j * 16;
                unsigned a0 = pA[2 * j][0];
                unsigned a1 = pA[2 * j][1];
                unsigned a2 = pA[2 * j + 1][0];
                unsigned a3 = pA[2 * j + 1][1];
#pragma unroll
                for (int nfp = 0; nfp < 4; nfp++) {
                    int mt = lane >> 3, ri = lane & 7;
                    const __half* vp = &Vs[kk + ri + ((mt & 1) << 3)][nfp * 16 + ((mt >> 1) << 3)];
                    unsigned r0, r1, r2, r3;
                    ldsm_x4_trans(r0, r1, r2, r3, vp);
                    int nf = nfp * 2;
                    mma_f16(o_acc[nf][0], o_acc[nf][1], o_acc[nf][2], o_acc[nf][3],
                            a0, a1, a2, a3, r0, r1);
                    mma_f16(o_acc[nf + 1][0], o_acc[nf + 1][1], o_acc[nf + 1][2], o_acc[nf + 1][3],
                            a0, a1, a2, a3, r2, r3);
                }
            }
        }
        __syncthreads();
    }

    float inv_l[2] = {1.f / l_i[0], 1.f / l_i[1]};
#pragma unroll
    for (int nf = 0; nf < 8; nf++)
#pragma unroll
        for (int eh = 0; eh < 2; eh++) {
            int t = qb * 128 + row0 + g + eh * 8;
            int d = nf * 8 + tig * 2;
            int m = t * BATCH + b;
            unsigned pv = pack_h2(o_acc[nf][eh * 2] * inv_l[eh],
                                  o_acc[nf][eh * 2 + 1] * inv_l[eh]);
            *(unsigned*)(&g_att[(size_t)m * DMODEL + hh * DHEAD + d]) = pv;
        }
}

// ---------------------------------------------------------------------------
// Kernel 3b: LayerNorm per row (1024 elems), two-pass, register-resident.
// ---------------------------------------------------------------------------
__device__ __forceinline__ float block_sum256(float v) {
    __shared__ float red[8];
#pragma unroll
    for (int off = 16; off > 0; off >>= 1) v += __shfl_xor_sync(0xffffffffu, v, off);
    if ((threadIdx.x & 31) == 0) red[threadIdx.x >> 5] = v;
    __syncthreads();
    v = red[0] + red[1] + red[2] + red[3] + red[4] + red[5] + red[6] + red[7];
    __syncthreads();
    return v;
}

__global__ __launch_bounds__(256) void layernorm_kernel(
    const float* __restrict__ lng, const float* __restrict__ lnb,
    float* __restrict__ out)
{
    const int row = blockIdx.x;
    const int tid = threadIdx.x;
    const float* x = g_res + (size_t)row * DMODEL;
    float4 v = *(const float4*)(x + tid * 4);
    float s = block_sum256(v.x + v.y + v.z + v.w);
    float mu = s * (1.f / DMODEL);
    float dx = v.x - mu, dy = v.y - mu, dz = v.z - mu, dw = v.w - mu;
    float sq = block_sum256(dx * dx + dy * dy + dz * dz + dw * dw);
    float var = sq * (1.f / DMODEL);
    float rstd = rsqrtf(var + 1e-5f);
    float4 gg = *(const float4*)(lng + tid * 4);
    float4 bb = *(const float4*)(lnb + tid * 4);
    float4 r;
    r.x = dx * rstd * gg.x + bb.x;
    r.y = dy * rstd * gg.y + bb.y;
    r.z = dz * rstd * gg.z + bb.z;
    r.w = dw * rstd * gg.w + bb.w;
    *(float4*)(out + (size_t)row * DMODEL + tid * 4) = r;
}

// ---------------------------------------------------------------------------
extern "C" void kernel_launch(void* const* d_in, const int* in_sizes, int n_in,
                              void* d_out, int out_size) {
    const float* h = (const float*)d_in[0];
    const int* mask = (const int*)d_in[1];
    const float* wq = (const float*)d_in[2];
    const float* wkv = (const float*)d_in[3];
    const float* wo = (const float*)d_in[4];
    const float* lng = (const float*)d_in[5];
    const float* lnb = (const float*)d_in[6];
    float* out = (float*)d_out;

    cudaFuncSetAttribute(flash_attn_kernel,
                         cudaFuncAttributeMaxDynamicSharedMemorySize, FLASH_SMEM_BYTES);
    cudaFuncSetAttribute(qkv_gemm_kernel,
                         cudaFuncAttributeMaxDynamicSharedMemorySize, GEMM_SMEM_BYTES);
    cudaFuncSetAttribute(outproj_gemm_kernel,
                         cudaFuncAttributeMaxDynamicSharedMemorySize, GEMM_SMEM_BYTES);

    conv_all_kernel<<<(TOT4 + T_LEN + 255) / 256, 256>>>(h, wq, wkv, wo, mask);
    qkv_gemm_kernel<<<dim3(64, 24), 256, GEMM_SMEM_BYTES>>>();
    flash_attn_kernel<<<dim3(16, 64), 256, FLASH_SMEM_BYTES>>>();
    outproj_gemm_kernel<<<dim3(64, 8), 256, GEMM_SMEM_BYTES>>>(h);
    layernorm_kernel<<<MROWS, 256>>>(lng, lnb, out);
}